// round 15
// baseline (speedup 1.0000x reference)
#include <cuda_runtime.h>
#include <cuda_fp16.h>
#include <cstdint>

typedef unsigned long long ull;

#define CDIM    256
#define HWDIM   1024
#define N_ROWS  32768
#define KCODES  1024

#define QUANT_OFF 1
#define PERP_OFF  8388609
#define ENC_OFF   8388610

#define DELTA   0.06f

// ---------------- scratch ----------------
__device__ __half         g_Eh[KCODES * CDIM];
__device__ float          g_Et[CDIM * KCODES];  // E transposed: [k][code], fp32
__device__ float          g_ee[KCODES];
__device__ ull            g_pKey[N_ROWS * 8];   // per (row, 128-col CTA tile) top1
__device__ float          g_pS2[N_ROWS * 8];    // per-tile runner-up score
__device__ int            g_rowIdx[N_ROWS];
__device__ int            g_rescueRows[N_ROWS];
__device__ int            g_nRescue;
__device__ unsigned int   g_counts[KCODES];
__device__ float          g_kldSum;

// ---------------- helpers ----------------
__device__ __forceinline__ uint32_t smem_u32(const void* p) {
    uint32_t a;
    asm("{ .reg .u64 t; cvta.to.shared.u64 t, %1; cvt.u32.u64 %0, t; }" : "=r"(a) : "l"(p));
    return a;
}
__device__ __forceinline__ void cp16(uint32_t dst, const void* src) {
    asm volatile("cp.async.cg.shared.global [%0], [%1], 16;" :: "r"(dst), "l"(src));
}
#define CP_COMMIT() asm volatile("cp.async.commit_group;" ::: "memory")
#define CP_WAIT1()  asm volatile("cp.async.wait_group 1;" ::: "memory")
#define CP_WAIT0()  asm volatile("cp.async.wait_group 0;" ::: "memory")

__device__ __forceinline__ void ldsm4(uint32_t* r, uint32_t a) {
    asm volatile("ldmatrix.sync.aligned.m8n8.x4.shared.b16 {%0,%1,%2,%3}, [%4];"
                 : "=r"(r[0]), "=r"(r[1]), "=r"(r[2]), "=r"(r[3]) : "r"(a));
}
__device__ __forceinline__ void mma_f16(float* c, uint32_t a0, uint32_t a1,
                                        uint32_t a2, uint32_t a3,
                                        uint32_t b0, uint32_t b1) {
    asm volatile("mma.sync.aligned.m16n8k16.row.col.f32.f16.f16.f32 "
                 "{%0,%1,%2,%3}, {%4,%5,%6,%7}, {%8,%9}, {%0,%1,%2,%3};"
                 : "+f"(c[0]), "+f"(c[1]), "+f"(c[2]), "+f"(c[3])
                 : "r"(a0), "r"(a1), "r"(a2), "r"(a3), "r"(b0), "r"(b1));
}

__device__ __forceinline__ ull packKey(float s, int idx) {
    unsigned u = __float_as_uint(s);
    u = (u & 0x80000000u) ? ~u : (u | 0x80000000u);
    return ((ull)u << 32) | (unsigned)(1023 - idx);
}
__device__ __forceinline__ float decodeKey(ull k) {
    unsigned u = (unsigned)(k >> 32);
    unsigned v = (u & 0x80000000u) ? (u & 0x7FFFFFFFu) : ~u;
    return __uint_as_float(v);
}
__device__ __forceinline__ unsigned fmap(float s) {
    unsigned u = __float_as_uint(s);
    return (u & 0x80000000u) ? ~u : (u | 0x80000000u);
}
__device__ __forceinline__ float funmap(unsigned u) {
    unsigned v = (u & 0x80000000u) ? (u & 0x7FFFFFFFu) : ~u;
    return __uint_as_float(v);
}

// -------- prep: E sum-of-squares + fp16 convert + scalar/count init ---------
__global__ void prepE(const float* __restrict__ E) {
    if (blockIdx.x == 0) {
        for (int t = threadIdx.x; t < KCODES; t += 256) g_counts[t] = 0u;
        if (threadIdx.x == 0) { g_kldSum = 0.0f; g_nRescue = 0; }
    }
    int gw   = (blockIdx.x * blockDim.x + threadIdx.x) >> 5;
    int lane = threadIdx.x & 31;
    if (gw >= KCODES) return;
    const float* p = E + (size_t)gw * CDIM;
    float4 a = *(const float4*)(p + (lane << 2));
    float4 b = *(const float4*)(p + 128 + (lane << 2));
    float s = a.x*a.x + a.y*a.y + a.z*a.z + a.w*a.w
            + b.x*b.x + b.y*b.y + b.z*b.z + b.w*b.w;
#pragma unroll
    for (int off = 16; off; off >>= 1) s += __shfl_xor_sync(0xFFFFFFFFu, s, off);
    if (lane == 0) g_ee[gw] = s;

    float va[8] = { a.x, a.y, a.z, a.w, b.x, b.y, b.z, b.w };
#pragma unroll
    for (int i = 0; i < 8; i++) {
        size_t o = (size_t)gw * CDIM + ((i < 4) ? (lane << 2) + i : 128 + (lane << 2) + i - 4);
        g_Eh[o] = __float2half_rn(va[i]);
    }
}

// -------- E transpose: Et[k][code] = E[code][k] (tiled, coalesced) ----------
__global__ void transposeE(const float* __restrict__ E) {
    __shared__ float t[32][33];
    int c0 = blockIdx.x << 5;   // code tile
    int k0 = blockIdx.y << 5;   // k tile
#pragma unroll
    for (int j = 0; j < 4; j++) {
        int cc = threadIdx.y + (j << 3);
        t[cc][threadIdx.x] = E[(size_t)(c0 + cc) * CDIM + k0 + threadIdx.x];
    }
    __syncthreads();
#pragma unroll
    for (int j = 0; j < 4; j++) {
        int kk = threadIdx.y + (j << 3);
        g_Et[(size_t)(k0 + kk) * KCODES + c0 + threadIdx.x] = t[threadIdx.x][kk];
    }
}

// ---------------- HMMA fp16 GEMM: A from NCHW input (fused transpose) -------
// Epilogue: G-read + top2 only (enc writes moved to finishKernel).
#define A_BYTES  65536
#define B_BYTES  16384
#define XX_OFF   (A_BYTES + 2 * B_BYTES)   // 98304
#define SMEM_DYN (XX_OFF + 512)            // 98816; 2 CTAs/SM
__global__ __launch_bounds__(256, 2)
void gemmKernel(const float* __restrict__ in, const float* __restrict__ G) {
    extern __shared__ char dsm[];
    const uint32_t sb = smem_u32(dsm);
    float* xxs = (float*)(dsm + XX_OFF);

    const int tid  = threadIdx.x;
    const int warp = tid >> 5;
    const int lane = tid & 31;
    const int wm   = warp >> 2;          // 0..1
    const int wn   = warp & 3;           // 0..3
    const int m0   = blockIdx.y << 7;
    const int j0   = blockIdx.x << 7;
    const int bb   = m0 >> 10;
    const int hw0  = m0 & 1023;
    const unsigned FULL = 0xFFFFFFFFu;

    if (tid < 128) xxs[tid] = 0.0f;

    auto loadB = [&](int c) {
        const int kb = c << 6;
        const uint32_t bBase = sb + A_BYTES + (uint32_t)(c & 1) * B_BYTES;
#pragma unroll
        for (int t = 0; t < 4; t++) {
            int id = tid + (t << 8);
            int r = id >> 3, k16 = id & 7;
            cp16(bBase + (uint32_t)r * 128u + (uint32_t)((k16 ^ (r & 7)) << 4),
                 g_Eh + (size_t)(j0 + r) * CDIM + kb + (k16 << 3));
        }
        CP_COMMIT();
    };

    loadB(0);
    loadB(1);
    __syncthreads();   // xxs zeros visible before atomics

    // ---- A: transpose+convert from NCHW input; fused ||x||^2 ----
    {
        const float* ibase = in + (size_t)bb * (CDIM * HWDIM) + hw0;
        float sq[4] = { 0.f, 0.f, 0.f, 0.f };
#pragma unroll 4
        for (int cc = 0; cc < 32; cc++) {
            int c = (warp << 5) + cc;
            uint32_t k16  = (uint32_t)(c >> 3);
            uint32_t coff = (uint32_t)((c & 7) << 1);
            const float* src = ibase + (size_t)c * HWDIM + lane;
#pragma unroll
            for (int hwg = 0; hwg < 4; hwg++) {
                float v = src[hwg << 5];
                uint32_t r = (uint32_t)((hwg << 5) + lane);
                uint32_t sw = (k16 & 24) | ((k16 ^ r) & 7);
                *(__half*)(dsm + r * 512u + sw * 16u + coff) = __float2half_rn(v);
                sq[hwg] += v * v;
            }
        }
#pragma unroll
        for (int hwg = 0; hwg < 4; hwg++)
            atomicAdd(&xxs[(hwg << 5) + lane], sq[hwg]);
    }

    float acc[4][4][4];
#pragma unroll
    for (int i = 0; i < 4; i++)
#pragma unroll
        for (int j = 0; j < 4; j++)
#pragma unroll
            for (int k = 0; k < 4; k++) acc[i][j][k] = 0.0f;

    __syncthreads();   // A tile + xxs complete

#pragma unroll 1
    for (int c = 0; c < 4; c++) {
        if (c < 3) { CP_WAIT1(); } else { CP_WAIT0(); }
        __syncthreads();

        const uint32_t bBase = sb + A_BYTES + (uint32_t)(c & 1) * B_BYTES;
#pragma unroll
        for (int ks = 0; ks < 4; ks++) {
            uint32_t bfr[4][2];
#pragma unroll
            for (int nfp = 0; nfp < 2; nfp++) {
                int g = lane >> 3;                    // 0..3
                int rowb = (wn << 5) + (nfp << 4) + ((g >> 1) << 3) + (lane & 7);
                int k16 = (ks << 1) + (g & 1);
                uint32_t addr = bBase + (uint32_t)rowb * 128u
                              + (uint32_t)((k16 ^ (rowb & 7)) << 4);
                uint32_t r4[4];
                ldsm4(r4, addr);
                bfr[(nfp << 1) + 0][0] = r4[0];
                bfr[(nfp << 1) + 0][1] = r4[1];
                bfr[(nfp << 1) + 1][0] = r4[2];
                bfr[(nfp << 1) + 1][1] = r4[3];
            }
#pragma unroll
            for (int mf = 0; mf < 4; mf++) {
                int rowa = (wm << 6) + (mf << 4) + (lane & 15);
                int k16  = (c << 3) + (ks << 1) + (lane >> 4);
                uint32_t sw = (uint32_t)((k16 & 24) | ((k16 ^ rowa) & 7));
                uint32_t afr[4];
                ldsm4(afr, sb + (uint32_t)rowa * 512u + (sw << 4));
#pragma unroll
                for (int nf = 0; nf < 4; nf++)
                    mma_f16(acc[mf][nf], afr[0], afr[1], afr[2], afr[3],
                            bfr[nf][0], bfr[nf][1]);
            }
        }
        __syncthreads();
        if (c + 2 < 4) loadB(c + 2);
    }

    // -------- stage accumulators to smem (fragment -> row-major) --------
    float* S = (float*)dsm;          // 128 x 132 floats = 67584 B
    {
        const int quad = lane >> 2;
        const int q    = lane & 3;
#pragma unroll
        for (int mf = 0; mf < 4; mf++)
#pragma unroll
            for (int half = 0; half < 2; half++) {
                int rl = (wm << 6) + (mf << 4) + quad + (half << 3);
#pragma unroll
                for (int nf = 0; nf < 4; nf++) {
                    int cl = (wn << 5) + (nf << 3) + (q << 1);
                    *(float2*)&S[rl * 132 + cl] =
                        make_float2(acc[mf][nf][half << 1], acc[mf][nf][(half << 1) + 1]);
                }
            }
    }
    __syncthreads();

    // ---- warp-per-row epilogue: G prefetch (MLP=8) + REDUX top-2 ----
    float kld = 0.0f;
    const int cbase = j0 + (lane << 2);
    const float4 e4 = *(const float4*)(g_ee + cbase);

#pragma unroll 1
    for (int batch = 0; batch < 2; batch++) {
        float4 gq[8];
#pragma unroll
        for (int r = 0; r < 8; r++) {
            int row = m0 + (warp << 4) + (batch << 3) + r;
            gq[r] = *(const float4*)(G + (size_t)row * KCODES + cbase);
        }
#pragma unroll
        for (int r = 0; r < 8; r++) {
            const int rl  = (warp << 4) + (batch << 3) + r;
            const int row = m0 + rl;
            const float xxr = xxs[rl];
            float4 a4 = *(const float4*)&S[rl * 132 + (lane << 2)];

            float dv[4] = { (xxr + e4.x) - 2.0f * a4.x, (xxr + e4.y) - 2.0f * a4.y,
                            (xxr + e4.z) - 2.0f * a4.z, (xxr + e4.w) - 2.0f * a4.w };
            float sv[4] = { gq[r].x - dv[0], gq[r].y - dv[1],
                            gq[r].z - dv[2], gq[r].w - dv[3] };
#pragma unroll
            for (int i = 0; i < 4; i++) {
                if (dv[i] < 85.0f) {
                    float pr = 1.0f / (1.0f + expf(dv[i]));
                    kld += pr * logf(fmaxf(pr, 1e-8f));
                }
            }
            float a1 = sv[0]; int i1 = 0; float a2 = -3.0e38f;
#pragma unroll
            for (int i = 1; i < 4; i++) {
                if (sv[i] > a1) { a2 = a1; a1 = sv[i]; i1 = i; }
                else            a2 = fmaxf(a2, sv[i]);
            }
            unsigned ms1 = fmap(a1);
            unsigned mx  = __reduce_max_sync(FULL, ms1);
            unsigned myi = (unsigned)(cbase + i1);
            unsigned wdx = __reduce_min_sync(FULL, (ms1 == mx) ? myi : 0xFFFFFFFFu);
            float cand = (ms1 == mx && myi == wdx) ? a2 : a1;
            unsigned m2 = __reduce_max_sync(FULL, fmap(cand));

            if (lane == 0) {
                int slot = (row << 3) + (int)blockIdx.x;
                g_pKey[slot] = ((ull)mx << 32) | (unsigned)(1023 - (int)wdx);
                g_pS2[slot]  = funmap(m2);
            }
        }
    }

#pragma unroll
    for (int off = 16; off; off >>= 1) kld += __shfl_down_sync(FULL, kld, off);
    if (lane == 0 && kld != 0.0f) atomicAdd(&g_kldSum, kld);
}

// ------- argmax: warp per row (8 slots); exact fp32 re-check of candidates ---
__global__ __launch_bounds__(256)
void argmaxKernel(const float* __restrict__ in, const float* __restrict__ E,
                  const float* __restrict__ G) {
    const int wid  = threadIdx.x >> 5;
    const int lane = threadIdx.x & 31;
    const int row  = (blockIdx.x << 3) + wid;
    const unsigned FULL = 0xFFFFFFFFu;

    ull   pk  = (lane < 8) ? g_pKey[(row << 3) + lane] : 0ull;
    float ps2 = (lane < 8) ? g_pS2[(row << 3) + lane] : -3.0e38f;

    ull best = pk;
#pragma unroll
    for (int off = 16; off; off >>= 1) best = max(best, __shfl_xor_sync(FULL, best, off));
    float sbest = decodeKey(best);
    float sc    = decodeKey(pk);   // NaN for lanes >= 8; fmaxf handles it
    float oth   = (pk == best) ? ps2 : fmaxf(sc, ps2);
#pragma unroll
    for (int off = 16; off; off >>= 1) oth = fmaxf(oth, __shfl_xor_sync(FULL, oth, off));

    if (sbest - oth >= DELTA) {   // warp-uniform
        if (lane == 0) g_rowIdx[row] = 1023 - (int)(unsigned)(best & 0xFFFFFFFFull);
        return;
    }
    if (__any_sync(FULL, ps2 >= sbest - DELTA)) {  // 3rd-place could hide
        if (lane == 0) {
            int p = atomicAdd(&g_nRescue, 1);
            g_rescueRows[p] = row;
        }
        return;
    }
    const int b  = row >> 10;
    const int hw = row & 1023;
    const float* xp = in + (size_t)b * CDIM * HWDIM + hw;
    float xr[8];
#pragma unroll
    for (int j = 0; j < 8; j++)
        xr[j] = xp[(size_t)((lane << 3) + j) * HWDIM];

    unsigned cm = __ballot_sync(FULL, sc >= sbest - DELTA);
    ull bestExact = 0ull;
    while (cm) {
        int src = __ffs(cm) - 1;
        cm &= cm - 1;
        ull ck = __shfl_sync(FULL, pk, src);
        int idx = 1023 - (int)(unsigned)(ck & 0xFFFFFFFFull);
        const float* e = E + (size_t)idx * CDIM + (lane << 3);
        float dot = 0.0f;
#pragma unroll
        for (int j = 0; j < 8; j++) dot = fmaf(xr[j], e[j], dot);
#pragma unroll
        for (int off = 16; off; off >>= 1) dot += __shfl_xor_sync(FULL, dot, off);
        float d = g_ee[idx] - 2.0f * dot;   // shift-free (xx row-constant)
        float s = G[(size_t)row * KCODES + idx] - d;
        bestExact = max(bestExact, packKey(s, idx));
    }
    if (lane == 0) g_rowIdx[row] = 1023 - (int)(unsigned)(bestExact & 0xFFFFFFFFull);
}

// ------- fp32 full-row rescue via Et (coalesced, FMA-bound), 8 rows/block ----
#define BR 8
__global__ __launch_bounds__(256)
void rescueKernel(const float* __restrict__ in, const float* __restrict__ G) {
    __shared__ float sx[BR][CDIM];
    __shared__ int   srow[BR];
    __shared__ ull   rwarp[8];
    const int tid  = threadIdx.x;
    const int lane = tid & 31;
    const int nR   = g_nRescue;

    for (int base = blockIdx.x * BR; base < nR; base += gridDim.x * BR) {
        const int nb = min(BR, nR - base);
        __syncthreads();   // protect sx reuse across outer iterations
        for (int r = 0; r < nb; r++) {
            int row = g_rescueRows[base + r];
            if (tid == 0) srow[r] = row;
            sx[r][tid] = in[(size_t)(row >> 10) * (CDIM * HWDIM)
                            + (size_t)tid * HWDIM + (row & 1023)];
        }
        __syncthreads();

        float acc[BR][4];
#pragma unroll
        for (int r = 0; r < BR; r++)
#pragma unroll
            for (int c4 = 0; c4 < 4; c4++) acc[r][c4] = 0.0f;

#pragma unroll 2
        for (int k = 0; k < CDIM; k++) {
            const float* et = g_Et + (size_t)k * KCODES + tid;
            float e0 = et[0];
            float e1 = et[256];
            float e2 = et[512];
            float e3 = et[768];
#pragma unroll
            for (int r = 0; r < BR; r++) {
                float xv = sx[r][k];
                acc[r][0] = fmaf(xv, e0, acc[r][0]);
                acc[r][1] = fmaf(xv, e1, acc[r][1]);
                acc[r][2] = fmaf(xv, e2, acc[r][2]);
                acc[r][3] = fmaf(xv, e3, acc[r][3]);
            }
        }

        for (int r = 0; r < nb; r++) {
            int row = srow[r];
            ull key = 0ull;
#pragma unroll
            for (int c4 = 0; c4 < 4; c4++) {
                int code = tid + (c4 << 8);
                float d = g_ee[code] - 2.0f * acc[r][c4];   // shift-free
                float s = G[(size_t)row * KCODES + code] - d;
                key = max(key, packKey(s, code));
            }
#pragma unroll
            for (int off = 16; off; off >>= 1)
                key = max(key, __shfl_down_sync(0xFFFFFFFFu, key, off));
            if (lane == 0) rwarp[tid >> 5] = key;
            __syncthreads();
            if (tid == 0) {
                ull b2 = rwarp[0];
#pragma unroll
                for (int w = 1; w < 8; w++) b2 = max(b2, rwarp[w]);
                g_rowIdx[row] = 1023 - (int)(unsigned)(b2 & 0xFFFFFFFFull);
            }
            __syncthreads();
        }
    }
}

// ---- finish: enc rows (zeros + embedded one-hot), quantized NCHW, histogram --
__global__ __launch_bounds__(256)
void finishKernel(const float* __restrict__ E, float* __restrict__ out) {
    __shared__ int   sIdx[32];
    __shared__ float sQ[32 * 257];

    const int n0  = blockIdx.x << 5;
    const int tid = threadIdx.x;

    if (tid < 32) {
        int idx = g_rowIdx[n0 + tid];
        sIdx[tid] = idx;
        atomicAdd(&g_counts[idx], 1u);
    }
    __syncthreads();

    // enc: write full rows, one-hot embedded (float2: base only 8B-aligned)
    float* enc = out + ENC_OFF;
#pragma unroll 1
    for (int i = 0; i < 32; i++) {
        const int idx = sIdx[i];
        float* erow = enc + (size_t)(n0 + i) * KCODES;
#pragma unroll
        for (int j = 0; j < 2; j++) {
            int col = ((j << 8) + tid) << 1;
            float2 v = make_float2(col == idx ? 1.0f : 0.0f,
                                   col + 1 == idx ? 1.0f : 0.0f);
            *(float2*)(erow + col) = v;
        }
    }

    const int c = tid;
#pragma unroll 4
    for (int i = 0; i < 32; i++)
        sQ[i * 257 + c] = E[(size_t)sIdx[i] * CDIM + c];
    __syncthreads();

    const int b   = n0 >> 10;
    const int hw0 = n0 & 1023;
    float* qb = out + QUANT_OFF + (size_t)b * CDIM * HWDIM;
#pragma unroll 4
    for (int it = 0; it < 32; it++) {
        int f  = it * 256 + tid;
        int cc = f >> 5;
        int ii = f & 31;
        qb[(size_t)cc * HWDIM + hw0 + ii] = sQ[ii * 257 + cc];
    }
}

// ---------------- scalars ----------------
// loss = C*(kld + e_lat*stopgrad(kld/clip(e_lat,1e-8))); e_lat >> 1e-8 always,
// so ratio == 1 exactly and loss = 3*kld.
__global__ void lossKernel(float* __restrict__ out) {
    __shared__ float red[32];
    int t = threadIdx.x;
    float avg  = (float)g_counts[t] * (1.0f / 32768.0f);
    float term = avg * logf(avg + 1e-10f);
#pragma unroll
    for (int off = 16; off; off >>= 1) term += __shfl_down_sync(0xFFFFFFFFu, term, off);
    if ((t & 31) == 0) red[t >> 5] = term;
    __syncthreads();
    if (t < 32) {
        float v = red[t];
#pragma unroll
        for (int off = 16; off; off >>= 1) v += __shfl_down_sync(0xFFFFFFFFu, v, off);
        if (t == 0) {
            float kld = g_kldSum * (1.0f / 32768.0f);
            out[0]        = 3.0f * kld;
            out[PERP_OFF] = expf(-v);
        }
    }
}

// ---------------- launch ----------------
extern "C" void kernel_launch(void* const* d_in, const int* in_sizes, int n_in,
                              void* d_out, int out_size) {
    const float* inp = (const float*)d_in[0];
    const float* emb = (const float*)d_in[1];
    const float* gum = (const float*)d_in[2];
    float* out = (float*)d_out;

    cudaFuncSetAttribute(gemmKernel, cudaFuncAttributeMaxDynamicSharedMemorySize, SMEM_DYN);

    prepE<<<128, 256>>>(emb);
    transposeE<<<dim3(32, 8), dim3(32, 8)>>>(emb);
    gemmKernel<<<dim3(KCODES / 128, N_ROWS / 128), 256, SMEM_DYN>>>(inp, gum);
    argmaxKernel<<<N_ROWS / 8, 256>>>(inp, emb, gum);
    rescueKernel<<<512, 256>>>(inp, gum);
    finishKernel<<<N_ROWS / 32, 256>>>(emb, out);
    lossKernel<<<1, 1024>>>(out);
}

// round 16
// speedup vs baseline: 1.1352x; 1.1352x over previous
#include <cuda_runtime.h>
#include <cuda_fp16.h>
#include <cstdint>

typedef unsigned long long ull;

#define CDIM    256
#define HWDIM   1024
#define N_ROWS  32768
#define KCODES  1024

#define QUANT_OFF 1
#define PERP_OFF  8388609
#define ENC_OFF   8388610

#define DELTA   0.06f

// ---------------- scratch ----------------
__device__ __half         g_Eh[KCODES * CDIM];
__device__ float          g_Et[CDIM * KCODES];  // E transposed: [k][code], fp32
__device__ float          g_ee[KCODES];
__device__ ull            g_pKey[N_ROWS * 8];   // per (row, 128-col CTA tile) top1
__device__ float          g_pS2[N_ROWS * 8];    // per-tile runner-up score
__device__ int            g_rowIdx[N_ROWS];
__device__ int            g_rescueRows[N_ROWS];
__device__ int            g_nRescue;
__device__ unsigned int   g_counts[KCODES];
__device__ float          g_kldSum;

// ---------------- helpers ----------------
__device__ __forceinline__ uint32_t smem_u32(const void* p) {
    uint32_t a;
    asm("{ .reg .u64 t; cvta.to.shared.u64 t, %1; cvt.u32.u64 %0, t; }" : "=r"(a) : "l"(p));
    return a;
}
__device__ __forceinline__ void cp16(uint32_t dst, const void* src) {
    asm volatile("cp.async.cg.shared.global [%0], [%1], 16;" :: "r"(dst), "l"(src));
}
#define CP_COMMIT() asm volatile("cp.async.commit_group;" ::: "memory")
#define CP_WAIT1()  asm volatile("cp.async.wait_group 1;" ::: "memory")
#define CP_WAIT0()  asm volatile("cp.async.wait_group 0;" ::: "memory")

__device__ __forceinline__ void ldsm4(uint32_t* r, uint32_t a) {
    asm volatile("ldmatrix.sync.aligned.m8n8.x4.shared.b16 {%0,%1,%2,%3}, [%4];"
                 : "=r"(r[0]), "=r"(r[1]), "=r"(r[2]), "=r"(r[3]) : "r"(a));
}
__device__ __forceinline__ void mma_f16(float* c, uint32_t a0, uint32_t a1,
                                        uint32_t a2, uint32_t a3,
                                        uint32_t b0, uint32_t b1) {
    asm volatile("mma.sync.aligned.m16n8k16.row.col.f32.f16.f16.f32 "
                 "{%0,%1,%2,%3}, {%4,%5,%6,%7}, {%8,%9}, {%0,%1,%2,%3};"
                 : "+f"(c[0]), "+f"(c[1]), "+f"(c[2]), "+f"(c[3])
                 : "r"(a0), "r"(a1), "r"(a2), "r"(a3), "r"(b0), "r"(b1));
}

__device__ __forceinline__ ull packKey(float s, int idx) {
    unsigned u = __float_as_uint(s);
    u = (u & 0x80000000u) ? ~u : (u | 0x80000000u);
    return ((ull)u << 32) | (unsigned)(1023 - idx);
}
__device__ __forceinline__ float decodeKey(ull k) {
    unsigned u = (unsigned)(k >> 32);
    unsigned v = (u & 0x80000000u) ? (u & 0x7FFFFFFFu) : ~u;
    return __uint_as_float(v);
}
__device__ __forceinline__ unsigned fmap(float s) {
    unsigned u = __float_as_uint(s);
    return (u & 0x80000000u) ? ~u : (u | 0x80000000u);
}
__device__ __forceinline__ float funmap(unsigned u) {
    unsigned v = (u & 0x80000000u) ? (u & 0x7FFFFFFFu) : ~u;
    return __uint_as_float(v);
}

// -------- prep: E sum-of-squares + fp16 convert + scalar/count init ---------
__global__ void prepE(const float* __restrict__ E) {
    if (blockIdx.x == 0) {
        for (int t = threadIdx.x; t < KCODES; t += 256) g_counts[t] = 0u;
        if (threadIdx.x == 0) { g_kldSum = 0.0f; g_nRescue = 0; }
    }
    int gw   = (blockIdx.x * blockDim.x + threadIdx.x) >> 5;
    int lane = threadIdx.x & 31;
    if (gw >= KCODES) return;
    const float* p = E + (size_t)gw * CDIM;
    float4 a = *(const float4*)(p + (lane << 2));
    float4 b = *(const float4*)(p + 128 + (lane << 2));
    float s = a.x*a.x + a.y*a.y + a.z*a.z + a.w*a.w
            + b.x*b.x + b.y*b.y + b.z*b.z + b.w*b.w;
#pragma unroll
    for (int off = 16; off; off >>= 1) s += __shfl_xor_sync(0xFFFFFFFFu, s, off);
    if (lane == 0) g_ee[gw] = s;

    float va[8] = { a.x, a.y, a.z, a.w, b.x, b.y, b.z, b.w };
#pragma unroll
    for (int i = 0; i < 8; i++) {
        size_t o = (size_t)gw * CDIM + ((i < 4) ? (lane << 2) + i : 128 + (lane << 2) + i - 4);
        g_Eh[o] = __float2half_rn(va[i]);
    }
}

// -------- E transpose: Et[k][code] = E[code][k] (tiled, coalesced) ----------
__global__ void transposeE(const float* __restrict__ E) {
    __shared__ float t[32][33];
    int c0 = blockIdx.x << 5;   // code tile
    int k0 = blockIdx.y << 5;   // k tile
#pragma unroll
    for (int j = 0; j < 4; j++) {
        int cc = threadIdx.y + (j << 3);
        t[cc][threadIdx.x] = E[(size_t)(c0 + cc) * CDIM + k0 + threadIdx.x];
    }
    __syncthreads();
#pragma unroll
    for (int j = 0; j < 4; j++) {
        int kk = threadIdx.y + (j << 3);
        g_Et[(size_t)(k0 + kk) * KCODES + c0 + threadIdx.x] = t[threadIdx.x][kk];
    }
}

// ---------------- HMMA fp16 GEMM: A from NCHW input (fused transpose) -------
// A-transpose: per thread, 8 consecutive c's for a fixed r -> one 16B store
// (<=4-way smem conflict via XOR swizzle) instead of 128x 2B 32-way stores.
#define A_BYTES  65536
#define B_BYTES  16384
#define XX_OFF   (A_BYTES + 2 * B_BYTES)   // 98304
#define SMEM_DYN (XX_OFF + 512)            // 98816; 2 CTAs/SM
__global__ __launch_bounds__(256, 2)
void gemmKernel(const float* __restrict__ in, const float* __restrict__ G,
                float* __restrict__ enc) {
    extern __shared__ char dsm[];
    const uint32_t sb = smem_u32(dsm);
    float* xxs = (float*)(dsm + XX_OFF);

    const int tid  = threadIdx.x;
    const int warp = tid >> 5;
    const int lane = tid & 31;
    const int wm   = warp >> 2;          // 0..1
    const int wn   = warp & 3;           // 0..3
    const int m0   = blockIdx.y << 7;
    const int j0   = blockIdx.x << 7;
    const int bb   = m0 >> 10;
    const int hw0  = m0 & 1023;
    const unsigned FULL = 0xFFFFFFFFu;

    if (tid < 128) xxs[tid] = 0.0f;

    auto loadB = [&](int c) {
        const int kb = c << 6;
        const uint32_t bBase = sb + A_BYTES + (uint32_t)(c & 1) * B_BYTES;
#pragma unroll
        for (int t = 0; t < 4; t++) {
            int id = tid + (t << 8);
            int r = id >> 3, k16 = id & 7;
            cp16(bBase + (uint32_t)r * 128u + (uint32_t)((k16 ^ (r & 7)) << 4),
                 g_Eh + (size_t)(j0 + r) * CDIM + kb + (k16 << 3));
        }
        CP_COMMIT();
    };

    loadB(0);
    loadB(1);
    __syncthreads();   // xxs zeros visible before atomics

    // ---- A: transpose+convert from NCHW input; fused ||x||^2 ----
    // warp owns c in [warp*32, warp*32+32); thread owns r = hwg*32+lane.
    {
        const float* ibase = in + (size_t)bb * (CDIM * HWDIM) + hw0;
        float sq[4] = { 0.f, 0.f, 0.f, 0.f };
        const int c0 = warp << 5;
#pragma unroll
        for (int k16i = 0; k16i < 4; k16i++) {
            const int cbase8 = c0 + (k16i << 3);
            const uint32_t k16 = (uint32_t)(cbase8 >> 3);
#pragma unroll
            for (int hwg = 0; hwg < 4; hwg++) {
                const int r = (hwg << 5) + lane;
                const float* src = ibase + r;
                float vv[8];
#pragma unroll
                for (int i = 0; i < 8; i++) {
                    vv[i] = src[(size_t)(cbase8 + i) * HWDIM];
                    sq[hwg] += vv[i] * vv[i];
                }
                __half2 h2[4];
#pragma unroll
                for (int i = 0; i < 4; i++)
                    h2[i] = __floats2half2_rn(vv[2 * i], vv[2 * i + 1]);
                uint32_t sw = (k16 & 24) | ((k16 ^ (uint32_t)r) & 7);
                *(uint4*)(dsm + (uint32_t)r * 512u + (sw << 4)) = *(uint4*)h2;
            }
        }
#pragma unroll
        for (int hwg = 0; hwg < 4; hwg++)
            atomicAdd(&xxs[(hwg << 5) + lane], sq[hwg]);
    }

    float acc[4][4][4];
#pragma unroll
    for (int i = 0; i < 4; i++)
#pragma unroll
        for (int j = 0; j < 4; j++)
#pragma unroll
            for (int k = 0; k < 4; k++) acc[i][j][k] = 0.0f;

    __syncthreads();   // A tile + xxs complete

#pragma unroll 1
    for (int c = 0; c < 4; c++) {
        if (c < 3) { CP_WAIT1(); } else { CP_WAIT0(); }
        __syncthreads();

        const uint32_t bBase = sb + A_BYTES + (uint32_t)(c & 1) * B_BYTES;
#pragma unroll
        for (int ks = 0; ks < 4; ks++) {
            uint32_t bfr[4][2];
#pragma unroll
            for (int nfp = 0; nfp < 2; nfp++) {
                int g = lane >> 3;                    // 0..3
                int rowb = (wn << 5) + (nfp << 4) + ((g >> 1) << 3) + (lane & 7);
                int k16 = (ks << 1) + (g & 1);
                uint32_t addr = bBase + (uint32_t)rowb * 128u
                              + (uint32_t)((k16 ^ (rowb & 7)) << 4);
                uint32_t r4[4];
                ldsm4(r4, addr);
                bfr[(nfp << 1) + 0][0] = r4[0];
                bfr[(nfp << 1) + 0][1] = r4[1];
                bfr[(nfp << 1) + 1][0] = r4[2];
                bfr[(nfp << 1) + 1][1] = r4[3];
            }
#pragma unroll
            for (int mf = 0; mf < 4; mf++) {
                int rowa = (wm << 6) + (mf << 4) + (lane & 15);
                int k16  = (c << 3) + (ks << 1) + (lane >> 4);
                uint32_t sw = (uint32_t)((k16 & 24) | ((k16 ^ rowa) & 7));
                uint32_t afr[4];
                ldsm4(afr, sb + (uint32_t)rowa * 512u + (sw << 4));
#pragma unroll
                for (int nf = 0; nf < 4; nf++)
                    mma_f16(acc[mf][nf], afr[0], afr[1], afr[2], afr[3],
                            bfr[nf][0], bfr[nf][1]);
            }
        }
        __syncthreads();
        if (c + 2 < 4) loadB(c + 2);
    }

    // -------- stage accumulators to smem (fragment -> row-major) --------
    float* S = (float*)dsm;          // 128 x 132 floats = 67584 B
    {
        const int quad = lane >> 2;
        const int q    = lane & 3;
#pragma unroll
        for (int mf = 0; mf < 4; mf++)
#pragma unroll
            for (int half = 0; half < 2; half++) {
                int rl = (wm << 6) + (mf << 4) + quad + (half << 3);
#pragma unroll
                for (int nf = 0; nf < 4; nf++) {
                    int cl = (wn << 5) + (nf << 3) + (q << 1);
                    *(float2*)&S[rl * 132 + cl] =
                        make_float2(acc[mf][nf][half << 1], acc[mf][nf][(half << 1) + 1]);
                }
            }
    }
    __syncthreads();

    // ---- warp-per-row epilogue: G prefetch (MLP=8) + REDX top-2 + enc zeros ----
    float kld = 0.0f;
    const float2 z2 = make_float2(0.f, 0.f);
    const int cbase = j0 + (lane << 2);
    const float4 e4 = *(const float4*)(g_ee + cbase);

#pragma unroll 1
    for (int batch = 0; batch < 2; batch++) {
        float4 gq[8];
#pragma unroll
        for (int r = 0; r < 8; r++) {
            int row = m0 + (warp << 4) + (batch << 3) + r;
            gq[r] = *(const float4*)(G + (size_t)row * KCODES + cbase);
        }
#pragma unroll
        for (int r = 0; r < 8; r++) {
            const int rl  = (warp << 4) + (batch << 3) + r;
            const int row = m0 + rl;
            const float xxr = xxs[rl];
            float4 a4 = *(const float4*)&S[rl * 132 + (lane << 2)];

            float dv[4] = { (xxr + e4.x) - 2.0f * a4.x, (xxr + e4.y) - 2.0f * a4.y,
                            (xxr + e4.z) - 2.0f * a4.z, (xxr + e4.w) - 2.0f * a4.w };
            float sv[4] = { gq[r].x - dv[0], gq[r].y - dv[1],
                            gq[r].z - dv[2], gq[r].w - dv[3] };
#pragma unroll
            for (int i = 0; i < 4; i++) {
                if (dv[i] < 85.0f) {
                    float pr = 1.0f / (1.0f + expf(dv[i]));
                    kld += pr * logf(fmaxf(pr, 1e-8f));
                }
            }
            float a1 = sv[0]; int i1 = 0; float a2 = -3.0e38f;
#pragma unroll
            for (int i = 1; i < 4; i++) {
                if (sv[i] > a1) { a2 = a1; a1 = sv[i]; i1 = i; }
                else            a2 = fmaxf(a2, sv[i]);
            }
            unsigned ms1 = fmap(a1);
            unsigned mx  = __reduce_max_sync(FULL, ms1);
            unsigned myi = (unsigned)(cbase + i1);
            unsigned wdx = __reduce_min_sync(FULL, (ms1 == mx) ? myi : 0xFFFFFFFFu);
            float cand = (ms1 == mx && myi == wdx) ? a2 : a1;
            unsigned m2 = __reduce_max_sync(FULL, fmap(cand));

            float* ep = enc + (size_t)row * KCODES + cbase;
            *(float2*)ep       = z2;
            *(float2*)(ep + 2) = z2;

            if (lane == 0) {
                int slot = (row << 3) + (int)blockIdx.x;
                g_pKey[slot] = ((ull)mx << 32) | (unsigned)(1023 - (int)wdx);
                g_pS2[slot]  = funmap(m2);
            }
        }
    }

#pragma unroll
    for (int off = 16; off; off >>= 1) kld += __shfl_down_sync(FULL, kld, off);
    if (lane == 0 && kld != 0.0f) atomicAdd(&g_kldSum, kld);
}

// ------- argmax: warp per row (8 slots); exact fp32 re-check of candidates ---
__global__ __launch_bounds__(256)
void argmaxKernel(const float* __restrict__ in, const float* __restrict__ E,
                  const float* __restrict__ G) {
    const int wid  = threadIdx.x >> 5;
    const int lane = threadIdx.x & 31;
    const int row  = (blockIdx.x << 3) + wid;
    const unsigned FULL = 0xFFFFFFFFu;

    ull   pk  = (lane < 8) ? g_pKey[(row << 3) + lane] : 0ull;
    float ps2 = (lane < 8) ? g_pS2[(row << 3) + lane] : -3.0e38f;

    ull best = pk;
#pragma unroll
    for (int off = 16; off; off >>= 1) best = max(best, __shfl_xor_sync(FULL, best, off));
    float sbest = decodeKey(best);
    float sc    = decodeKey(pk);   // NaN for lanes >= 8; fmaxf handles it
    float oth   = (pk == best) ? ps2 : fmaxf(sc, ps2);
#pragma unroll
    for (int off = 16; off; off >>= 1) oth = fmaxf(oth, __shfl_xor_sync(FULL, oth, off));

    if (sbest - oth >= DELTA) {   // warp-uniform
        if (lane == 0) g_rowIdx[row] = 1023 - (int)(unsigned)(best & 0xFFFFFFFFull);
        return;
    }
    if (__any_sync(FULL, ps2 >= sbest - DELTA)) {  // 3rd-place could hide
        if (lane == 0) {
            int p = atomicAdd(&g_nRescue, 1);
            g_rescueRows[p] = row;
        }
        return;
    }
    const int b  = row >> 10;
    const int hw = row & 1023;
    const float* xp = in + (size_t)b * CDIM * HWDIM + hw;
    float xr[8];
#pragma unroll
    for (int j = 0; j < 8; j++)
        xr[j] = xp[(size_t)((lane << 3) + j) * HWDIM];

    unsigned cm = __ballot_sync(FULL, sc >= sbest - DELTA);
    ull bestExact = 0ull;
    while (cm) {
        int src = __ffs(cm) - 1;
        cm &= cm - 1;
        ull ck = __shfl_sync(FULL, pk, src);
        int idx = 1023 - (int)(unsigned)(ck & 0xFFFFFFFFull);
        const float* e = E + (size_t)idx * CDIM + (lane << 3);
        float dot = 0.0f;
#pragma unroll
        for (int j = 0; j < 8; j++) dot = fmaf(xr[j], e[j], dot);
#pragma unroll
        for (int off = 16; off; off >>= 1) dot += __shfl_xor_sync(FULL, dot, off);
        float d = g_ee[idx] - 2.0f * dot;   // shift-free (xx row-constant)
        float s = G[(size_t)row * KCODES + idx] - d;
        bestExact = max(bestExact, packKey(s, idx));
    }
    if (lane == 0) g_rowIdx[row] = 1023 - (int)(unsigned)(bestExact & 0xFFFFFFFFull);
}

// ------- fp32 full-row rescue via Et (coalesced, FMA-bound), 8 rows/block ----
#define BR 8
__global__ __launch_bounds__(256)
void rescueKernel(const float* __restrict__ in, const float* __restrict__ G) {
    __shared__ float sx[BR][CDIM];
    __shared__ int   srow[BR];
    __shared__ ull   rwarp[8];
    const int tid  = threadIdx.x;
    const int lane = tid & 31;
    const int nR   = g_nRescue;

    for (int base = blockIdx.x * BR; base < nR; base += gridDim.x * BR) {
        const int nb = min(BR, nR - base);
        __syncthreads();   // protect sx reuse across outer iterations
        for (int r = 0; r < nb; r++) {
            int row = g_rescueRows[base + r];
            if (tid == 0) srow[r] = row;
            sx[r][tid] = in[(size_t)(row >> 10) * (CDIM * HWDIM)
                            + (size_t)tid * HWDIM + (row & 1023)];
        }
        __syncthreads();

        float acc[BR][4];
#pragma unroll
        for (int r = 0; r < BR; r++)
#pragma unroll
            for (int c4 = 0; c4 < 4; c4++) acc[r][c4] = 0.0f;

#pragma unroll 2
        for (int k = 0; k < CDIM; k++) {
            const float* et = g_Et + (size_t)k * KCODES + tid;
            float e0 = et[0];
            float e1 = et[256];
            float e2 = et[512];
            float e3 = et[768];
#pragma unroll
            for (int r = 0; r < BR; r++) {
                float xv = sx[r][k];
                acc[r][0] = fmaf(xv, e0, acc[r][0]);
                acc[r][1] = fmaf(xv, e1, acc[r][1]);
                acc[r][2] = fmaf(xv, e2, acc[r][2]);
                acc[r][3] = fmaf(xv, e3, acc[r][3]);
            }
        }

        for (int r = 0; r < nb; r++) {
            int row = srow[r];
            ull key = 0ull;
#pragma unroll
            for (int c4 = 0; c4 < 4; c4++) {
                int code = tid + (c4 << 8);
                float d = g_ee[code] - 2.0f * acc[r][c4];   // shift-free
                float s = G[(size_t)row * KCODES + code] - d;
                key = max(key, packKey(s, code));
            }
#pragma unroll
            for (int off = 16; off; off >>= 1)
                key = max(key, __shfl_down_sync(0xFFFFFFFFu, key, off));
            if (lane == 0) rwarp[tid >> 5] = key;
            __syncthreads();
            if (tid == 0) {
                ull b2 = rwarp[0];
#pragma unroll
                for (int w = 1; w < 8; w++) b2 = max(b2, rwarp[w]);
                g_rowIdx[row] = 1023 - (int)(unsigned)(b2 & 0xFFFFFFFFull);
            }
            __syncthreads();
        }
    }
}

// ---------------- finish: one-hot scatter, quantized NCHW, histogram ----------
__global__ __launch_bounds__(256)
void finishKernel(const float* __restrict__ E, float* __restrict__ out) {
    __shared__ int   sIdx[32];
    __shared__ float sQ[32 * 257];

    const int n0  = blockIdx.x << 5;
    const int tid = threadIdx.x;

    if (tid < 32) {
        int idx = g_rowIdx[n0 + tid];
        sIdx[tid] = idx;
        out[ENC_OFF + (size_t)(n0 + tid) * KCODES + idx] = 1.0f;
        atomicAdd(&g_counts[idx], 1u);
    }
    __syncthreads();

    const int c = tid;
#pragma unroll 4
    for (int i = 0; i < 32; i++)
        sQ[i * 257 + c] = E[(size_t)sIdx[i] * CDIM + c];
    __syncthreads();

    const int b   = n0 >> 10;
    const int hw0 = n0 & 1023;
    float* qb = out + QUANT_OFF + (size_t)b * CDIM * HWDIM;
#pragma unroll 4
    for (int it = 0; it < 32; it++) {
        int f  = it * 256 + tid;
        int cc = f >> 5;
        int ii = f & 31;
        qb[(size_t)cc * HWDIM + hw0 + ii] = sQ[ii * 257 + cc];
    }
}

// ---------------- scalars ----------------
// loss = C*(kld + e_lat*stopgrad(kld/clip(e_lat,1e-8))); e_lat >> 1e-8 always,
// so ratio == 1 exactly and loss = 3*kld.
__global__ void lossKernel(float* __restrict__ out) {
    __shared__ float red[32];
    int t = threadIdx.x;
    float avg  = (float)g_counts[t] * (1.0f / 32768.0f);
    float term = avg * logf(avg + 1e-10f);
#pragma unroll
    for (int off = 16; off; off >>= 1) term += __shfl_down_sync(0xFFFFFFFFu, term, off);
    if ((t & 31) == 0) red[t >> 5] = term;
    __syncthreads();
    if (t < 32) {
        float v = red[t];
#pragma unroll
        for (int off = 16; off; off >>= 1) v += __shfl_down_sync(0xFFFFFFFFu, v, off);
        if (t == 0) {
            float kld = g_kldSum * (1.0f / 32768.0f);
            out[0]        = 3.0f * kld;
            out[PERP_OFF] = expf(-v);
        }
    }
}

// ---------------- launch ----------------
extern "C" void kernel_launch(void* const* d_in, const int* in_sizes, int n_in,
                              void* d_out, int out_size) {
    const float* inp = (const float*)d_in[0];
    const float* emb = (const float*)d_in[1];
    const float* gum = (const float*)d_in[2];
    float* out = (float*)d_out;
    float* enc = out + ENC_OFF;

    cudaFuncSetAttribute(gemmKernel, cudaFuncAttributeMaxDynamicSharedMemorySize, SMEM_DYN);

    prepE<<<128, 256>>>(emb);
    transposeE<<<dim3(32, 8), dim3(32, 8)>>>(emb);
    gemmKernel<<<dim3(KCODES / 128, N_ROWS / 128), 256, SMEM_DYN>>>(inp, gum, enc);
    argmaxKernel<<<N_ROWS / 8, 256>>>(inp, emb, gum);
    rescueKernel<<<512, 256>>>(inp, gum);
    finishKernel<<<N_ROWS / 32, 256>>>(emb, out);
    lossKernel<<<1, 1024>>>(out);
}

// round 17
// speedup vs baseline: 1.1636x; 1.0251x over previous
#include <cuda_runtime.h>
#include <cuda_fp16.h>
#include <cstdint>

typedef unsigned long long ull;

#define CDIM    256
#define HWDIM   1024
#define N_ROWS  32768
#define KCODES  1024

#define QUANT_OFF 1
#define PERP_OFF  8388609
#define ENC_OFF   8388610

#define DELTA   0.06f

// ---------------- scratch ----------------
__device__ __half         g_Eh[KCODES * CDIM];
__device__ float          g_Et[CDIM * KCODES];  // E transposed: [k][code], fp32
__device__ float          g_ee[KCODES];
__device__ ull            g_pKey[N_ROWS * 8];   // per (row, 128-col tile) top1
__device__ float          g_pS2[N_ROWS * 8];    // per-tile runner-up score
__device__ int            g_rowIdx[N_ROWS];
__device__ int            g_rescueRows[N_ROWS];
__device__ int            g_nRescue;
__device__ unsigned int   g_counts[KCODES];
__device__ float          g_kldSum;

// ---------------- helpers ----------------
__device__ __forceinline__ uint32_t smem_u32(const void* p) {
    uint32_t a;
    asm("{ .reg .u64 t; cvta.to.shared.u64 t, %1; cvt.u32.u64 %0, t; }" : "=r"(a) : "l"(p));
    return a;
}
__device__ __forceinline__ void cp16(uint32_t dst, const void* src) {
    asm volatile("cp.async.cg.shared.global [%0], [%1], 16;" :: "r"(dst), "l"(src));
}
#define CP_COMMIT() asm volatile("cp.async.commit_group;" ::: "memory")
#define CP_WAIT1()  asm volatile("cp.async.wait_group 1;" ::: "memory")
#define CP_WAIT0()  asm volatile("cp.async.wait_group 0;" ::: "memory")

__device__ __forceinline__ void ldsm4(uint32_t* r, uint32_t a) {
    asm volatile("ldmatrix.sync.aligned.m8n8.x4.shared.b16 {%0,%1,%2,%3}, [%4];"
                 : "=r"(r[0]), "=r"(r[1]), "=r"(r[2]), "=r"(r[3]) : "r"(a));
}
__device__ __forceinline__ void mma_f16(float* c, uint32_t a0, uint32_t a1,
                                        uint32_t a2, uint32_t a3,
                                        uint32_t b0, uint32_t b1) {
    asm volatile("mma.sync.aligned.m16n8k16.row.col.f32.f16.f16.f32 "
                 "{%0,%1,%2,%3}, {%4,%5,%6,%7}, {%8,%9}, {%0,%1,%2,%3};"
                 : "+f"(c[0]), "+f"(c[1]), "+f"(c[2]), "+f"(c[3])
                 : "r"(a0), "r"(a1), "r"(a2), "r"(a3), "r"(b0), "r"(b1));
}

__device__ __forceinline__ ull packKey(float s, int idx) {
    unsigned u = __float_as_uint(s);
    u = (u & 0x80000000u) ? ~u : (u | 0x80000000u);
    return ((ull)u << 32) | (unsigned)(1023 - idx);
}
__device__ __forceinline__ float decodeKey(ull k) {
    unsigned u = (unsigned)(k >> 32);
    unsigned v = (u & 0x80000000u) ? (u & 0x7FFFFFFFu) : ~u;
    return __uint_as_float(v);
}
__device__ __forceinline__ unsigned fmap(float s) {
    unsigned u = __float_as_uint(s);
    return (u & 0x80000000u) ? ~u : (u | 0x80000000u);
}
__device__ __forceinline__ float funmap(unsigned u) {
    unsigned v = (u & 0x80000000u) ? (u & 0x7FFFFFFFu) : ~u;
    return __uint_as_float(v);
}

// ---- prep (merged): E transpose tile + sumsq/fp16 convert + init ----
__global__ void prepE(const float* __restrict__ E) {
    __shared__ float t[32][33];
    const int bid = blockIdx.x;        // 256 blocks
    const int tx  = threadIdx.x & 31;
    const int ty  = threadIdx.x >> 5;  // 0..7
    const int c0  = (bid & 31) << 5;   // code tile
    const int k0  = (bid >> 5) << 5;   // k tile
#pragma unroll
    for (int j = 0; j < 4; j++) {
        int cc = ty + (j << 3);
        t[cc][tx] = E[(size_t)(c0 + cc) * CDIM + k0 + tx];
    }
    __syncthreads();
#pragma unroll
    for (int j = 0; j < 4; j++) {
        int kk = ty + (j << 3);
        g_Et[(size_t)(k0 + kk) * KCODES + c0 + tx] = t[tx][kk];
    }

    if (bid == 0) {
        for (int q = threadIdx.x; q < KCODES; q += 256) g_counts[q] = 0u;
        if (threadIdx.x == 0) { g_kldSum = 0.0f; g_nRescue = 0; }
    }
    if (bid < 128) {
        int gw   = ((bid << 8) + threadIdx.x) >> 5;
        int lane = threadIdx.x & 31;
        const float* p = E + (size_t)gw * CDIM;
        float4 a = *(const float4*)(p + (lane << 2));
        float4 b = *(const float4*)(p + 128 + (lane << 2));
        float s = a.x*a.x + a.y*a.y + a.z*a.z + a.w*a.w
                + b.x*b.x + b.y*b.y + b.z*b.z + b.w*b.w;
#pragma unroll
        for (int off = 16; off; off >>= 1) s += __shfl_xor_sync(0xFFFFFFFFu, s, off);
        if (lane == 0) g_ee[gw] = s;

        float va[8] = { a.x, a.y, a.z, a.w, b.x, b.y, b.z, b.w };
#pragma unroll
        for (int i = 0; i < 8; i++) {
            size_t o = (size_t)gw * CDIM +
                       ((i < 4) ? (lane << 2) + i : 128 + (lane << 2) + i - 4);
            g_Eh[o] = __float2half_rn(va[i]);
        }
    }
}

// ---------------- HMMA fp16 GEMM: M=64 tiles, 3 CTAs/SM -------
// CTA: 64 rows x 128 codes, 8 warps (2x4), warp 32x32. 4 K-chunks of 64.
// A: 64x256 fp16 from NCHW input (fused transpose, one 16B store per group).
// B: 2-stage cp.async ring. Epilogue: staged S + warp-per-row REDUX top-2.
#define A_BYTES  32768
#define B_BYTES  16384
#define XX_OFF   (A_BYTES + 2 * B_BYTES)   // 65536
#define SMEM_DYN (XX_OFF + 256)            // 65792; 3 CTAs/SM = 197376
__global__ __launch_bounds__(256, 3)
void gemmKernel(const float* __restrict__ in, const float* __restrict__ G,
                float* __restrict__ enc) {
    extern __shared__ char dsm[];
    const uint32_t sb = smem_u32(dsm);
    float* xxs = (float*)(dsm + XX_OFF);

    const int tid  = threadIdx.x;
    const int warp = tid >> 5;
    const int lane = tid & 31;
    const int wm   = warp >> 2;          // 0..1 (32-row halves)
    const int wn   = warp & 3;           // 0..3 (32-col strips)
    const int m0   = blockIdx.y << 6;    // 64-row tile
    const int j0   = blockIdx.x << 7;
    const int bb   = m0 >> 10;
    const int hw0  = m0 & 1023;
    const unsigned FULL = 0xFFFFFFFFu;

    if (tid < 64) xxs[tid] = 0.0f;

    auto loadB = [&](int c) {
        const int kb = c << 6;
        const uint32_t bBase = sb + A_BYTES + (uint32_t)(c & 1) * B_BYTES;
#pragma unroll
        for (int t = 0; t < 4; t++) {
            int id = tid + (t << 8);
            int r = id >> 3, k16 = id & 7;
            cp16(bBase + (uint32_t)r * 128u + (uint32_t)((k16 ^ (r & 7)) << 4),
                 g_Eh + (size_t)(j0 + r) * CDIM + kb + (k16 << 3));
        }
        CP_COMMIT();
    };

    loadB(0);
    loadB(1);
    __syncthreads();   // xxs zeros visible before atomics

    // ---- A: transpose+convert from NCHW input; fused ||x||^2 ----
    // warp owns c in [warp*32, warp*32+32); thread owns r = hwg*32+lane (64 rows)
    {
        const float* ibase = in + (size_t)bb * (CDIM * HWDIM) + hw0;
        float sq[2] = { 0.f, 0.f };
        const int c0 = warp << 5;
#pragma unroll
        for (int k16i = 0; k16i < 4; k16i++) {
            const int cbase8 = c0 + (k16i << 3);
            const uint32_t k16 = (uint32_t)(cbase8 >> 3);
#pragma unroll
            for (int hwg = 0; hwg < 2; hwg++) {
                const int r = (hwg << 5) + lane;
                const float* src = ibase + r;
                float vv[8];
#pragma unroll
                for (int i = 0; i < 8; i++) {
                    vv[i] = src[(size_t)(cbase8 + i) * HWDIM];
                    sq[hwg] += vv[i] * vv[i];
                }
                __half2 h2[4];
#pragma unroll
                for (int i = 0; i < 4; i++)
                    h2[i] = __floats2half2_rn(vv[2 * i], vv[2 * i + 1]);
                uint32_t sw = (k16 & 24) | ((k16 ^ (uint32_t)r) & 7);
                *(uint4*)(dsm + (uint32_t)r * 512u + (sw << 4)) = *(uint4*)h2;
            }
        }
#pragma unroll
        for (int hwg = 0; hwg < 2; hwg++)
            atomicAdd(&xxs[(hwg << 5) + lane], sq[hwg]);
    }

    float acc[2][4][4];
#pragma unroll
    for (int i = 0; i < 2; i++)
#pragma unroll
        for (int j = 0; j < 4; j++)
#pragma unroll
            for (int k = 0; k < 4; k++) acc[i][j][k] = 0.0f;

    __syncthreads();   // A tile + xxs complete

#pragma unroll 1
    for (int c = 0; c < 4; c++) {
        if (c < 3) { CP_WAIT1(); } else { CP_WAIT0(); }
        __syncthreads();

        const uint32_t bBase = sb + A_BYTES + (uint32_t)(c & 1) * B_BYTES;
#pragma unroll
        for (int ks = 0; ks < 4; ks++) {
            uint32_t bfr[4][2];
#pragma unroll
            for (int nfp = 0; nfp < 2; nfp++) {
                int g = lane >> 3;                    // 0..3
                int rowb = (wn << 5) + (nfp << 4) + ((g >> 1) << 3) + (lane & 7);
                int k16 = (ks << 1) + (g & 1);
                uint32_t addr = bBase + (uint32_t)rowb * 128u
                              + (uint32_t)((k16 ^ (rowb & 7)) << 4);
                uint32_t r4[4];
                ldsm4(r4, addr);
                bfr[(nfp << 1) + 0][0] = r4[0];
                bfr[(nfp << 1) + 0][1] = r4[1];
                bfr[(nfp << 1) + 1][0] = r4[2];
                bfr[(nfp << 1) + 1][1] = r4[3];
            }
#pragma unroll
            for (int mf = 0; mf < 2; mf++) {
                int rowa = (wm << 5) + (mf << 4) + (lane & 15);
                int k16  = (c << 3) + (ks << 1) + (lane >> 4);
                uint32_t sw = (uint32_t)((k16 & 24) | ((k16 ^ rowa) & 7));
                uint32_t afr[4];
                ldsm4(afr, sb + (uint32_t)rowa * 512u + (sw << 4));
#pragma unroll
                for (int nf = 0; nf < 4; nf++)
                    mma_f16(acc[mf][nf], afr[0], afr[1], afr[2], afr[3],
                            bfr[nf][0], bfr[nf][1]);
            }
        }
        __syncthreads();
        if (c + 2 < 4) loadB(c + 2);
    }

    // -------- stage accumulators to smem (fragment -> row-major) --------
    // S = 64 x 132 floats = 33792 B, overlays dead A + B stage0; xxs untouched.
    float* S = (float*)dsm;
    {
        const int quad = lane >> 2;
        const int q    = lane & 3;
#pragma unroll
        for (int mf = 0; mf < 2; mf++)
#pragma unroll
            for (int half = 0; half < 2; half++) {
                int rl = (wm << 5) + (mf << 4) + quad + (half << 3);
#pragma unroll
                for (int nf = 0; nf < 4; nf++) {
                    int cl = (wn << 5) + (nf << 3) + (q << 1);
                    *(float2*)&S[rl * 132 + cl] =
                        make_float2(acc[mf][nf][half << 1], acc[mf][nf][(half << 1) + 1]);
                }
            }
    }
    __syncthreads();

    // ---- warp-per-row epilogue: G prefetch (MLP=8) + REDUX top-2 + enc zeros ----
    float kld = 0.0f;
    const float2 z2 = make_float2(0.f, 0.f);
    const int cbase = j0 + (lane << 2);
    const float4 e4 = *(const float4*)(g_ee + cbase);

    {
        float4 gq[8];
#pragma unroll
        for (int r = 0; r < 8; r++) {
            int row = m0 + (warp << 3) + r;
            gq[r] = *(const float4*)(G + (size_t)row * KCODES + cbase);
        }
#pragma unroll
        for (int r = 0; r < 8; r++) {
            const int rl  = (warp << 3) + r;
            const int row = m0 + rl;
            const float xxr = xxs[rl];
            float4 a4 = *(const float4*)&S[rl * 132 + (lane << 2)];

            float dv[4] = { (xxr + e4.x) - 2.0f * a4.x, (xxr + e4.y) - 2.0f * a4.y,
                            (xxr + e4.z) - 2.0f * a4.z, (xxr + e4.w) - 2.0f * a4.w };
            float sv[4] = { gq[r].x - dv[0], gq[r].y - dv[1],
                            gq[r].z - dv[2], gq[r].w - dv[3] };
#pragma unroll
            for (int i = 0; i < 4; i++) {
                if (dv[i] < 85.0f) {
                    float pr = 1.0f / (1.0f + expf(dv[i]));
                    kld += pr * logf(fmaxf(pr, 1e-8f));
                }
            }
            float a1 = sv[0]; int i1 = 0; float a2 = -3.0e38f;
#pragma unroll
            for (int i = 1; i < 4; i++) {
                if (sv[i] > a1) { a2 = a1; a1 = sv[i]; i1 = i; }
                else            a2 = fmaxf(a2, sv[i]);
            }
            unsigned ms1 = fmap(a1);
            unsigned mx  = __reduce_max_sync(FULL, ms1);
            unsigned myi = (unsigned)(cbase + i1);
            unsigned wdx = __reduce_min_sync(FULL, (ms1 == mx) ? myi : 0xFFFFFFFFu);
            float cand = (ms1 == mx && myi == wdx) ? a2 : a1;
            unsigned m2 = __reduce_max_sync(FULL, fmap(cand));

            float* ep = enc + (size_t)row * KCODES + cbase;
            *(float2*)ep       = z2;
            *(float2*)(ep + 2) = z2;

            if (lane == 0) {
                int slot = (row << 3) + (int)blockIdx.x;
                g_pKey[slot] = ((ull)mx << 32) | (unsigned)(1023 - (int)wdx);
                g_pS2[slot]  = funmap(m2);
            }
        }
    }

#pragma unroll
    for (int off = 16; off; off >>= 1) kld += __shfl_down_sync(FULL, kld, off);
    if (lane == 0 && kld != 0.0f) atomicAdd(&g_kldSum, kld);
}

// ------- argmax: warp per row (8 slots); exact fp32 re-check of candidates ---
__global__ __launch_bounds__(256)
void argmaxKernel(const float* __restrict__ in, const float* __restrict__ E,
                  const float* __restrict__ G) {
    const int wid  = threadIdx.x >> 5;
    const int lane = threadIdx.x & 31;
    const int row  = (blockIdx.x << 3) + wid;
    const unsigned FULL = 0xFFFFFFFFu;

    ull   pk  = (lane < 8) ? g_pKey[(row << 3) + lane] : 0ull;
    float ps2 = (lane < 8) ? g_pS2[(row << 3) + lane] : -3.0e38f;

    ull best = pk;
#pragma unroll
    for (int off = 16; off; off >>= 1) best = max(best, __shfl_xor_sync(FULL, best, off));
    float sbest = decodeKey(best);
    float sc    = decodeKey(pk);   // NaN for lanes >= 8; fmaxf handles it
    float oth   = (pk == best) ? ps2 : fmaxf(sc, ps2);
#pragma unroll
    for (int off = 16; off; off >>= 1) oth = fmaxf(oth, __shfl_xor_sync(FULL, oth, off));

    if (sbest - oth >= DELTA) {   // warp-uniform
        if (lane == 0) g_rowIdx[row] = 1023 - (int)(unsigned)(best & 0xFFFFFFFFull);
        return;
    }
    if (__any_sync(FULL, ps2 >= sbest - DELTA)) {  // 3rd-place could hide
        if (lane == 0) {
            int p = atomicAdd(&g_nRescue, 1);
            g_rescueRows[p] = row;
        }
        return;
    }
    const int b  = row >> 10;
    const int hw = row & 1023;
    const float* xp = in + (size_t)b * CDIM * HWDIM + hw;
    float xr[8];
#pragma unroll
    for (int j = 0; j < 8; j++)
        xr[j] = xp[(size_t)((lane << 3) + j) * HWDIM];

    unsigned cm = __ballot_sync(FULL, sc >= sbest - DELTA);
    ull bestExact = 0ull;
    while (cm) {
        int src = __ffs(cm) - 1;
        cm &= cm - 1;
        ull ck = __shfl_sync(FULL, pk, src);
        int idx = 1023 - (int)(unsigned)(ck & 0xFFFFFFFFull);
        const float* e = E + (size_t)idx * CDIM + (lane << 3);
        float dot = 0.0f;
#pragma unroll
        for (int j = 0; j < 8; j++) dot = fmaf(xr[j], e[j], dot);
#pragma unroll
        for (int off = 16; off; off >>= 1) dot += __shfl_xor_sync(FULL, dot, off);
        float d = g_ee[idx] - 2.0f * dot;   // shift-free (xx row-constant)
        float s = G[(size_t)row * KCODES + idx] - d;
        bestExact = max(bestExact, packKey(s, idx));
    }
    if (lane == 0) g_rowIdx[row] = 1023 - (int)(unsigned)(bestExact & 0xFFFFFFFFull);
}

// ------- fp32 full-row rescue via Et (coalesced, FMA-bound), 8 rows/block ----
#define BR 8
__global__ __launch_bounds__(256)
void rescueKernel(const float* __restrict__ in, const float* __restrict__ G) {
    __shared__ float sx[BR][CDIM];
    __shared__ int   srow[BR];
    __shared__ ull   rwarp[8];
    const int tid  = threadIdx.x;
    const int lane = tid & 31;
    const int nR   = g_nRescue;

    for (int base = blockIdx.x * BR; base < nR; base += gridDim.x * BR) {
        const int nb = min(BR, nR - base);
        __syncthreads();   // protect sx reuse across outer iterations
        for (int r = 0; r < nb; r++) {
            int row = g_rescueRows[base + r];
            if (tid == 0) srow[r] = row;
            sx[r][tid] = in[(size_t)(row >> 10) * (CDIM * HWDIM)
                            + (size_t)tid * HWDIM + (row & 1023)];
        }
        __syncthreads();

        float acc[BR][4];
#pragma unroll
        for (int r = 0; r < BR; r++)
#pragma unroll
            for (int c4 = 0; c4 < 4; c4++) acc[r][c4] = 0.0f;

#pragma unroll 2
        for (int k = 0; k < CDIM; k++) {
            const float* et = g_Et + (size_t)k * KCODES + tid;
            float e0 = et[0];
            float e1 = et[256];
            float e2 = et[512];
            float e3 = et[768];
#pragma unroll
            for (int r = 0; r < BR; r++) {
                float xv = sx[r][k];
                acc[r][0] = fmaf(xv, e0, acc[r][0]);
                acc[r][1] = fmaf(xv, e1, acc[r][1]);
                acc[r][2] = fmaf(xv, e2, acc[r][2]);
                acc[r][3] = fmaf(xv, e3, acc[r][3]);
            }
        }

        for (int r = 0; r < nb; r++) {
            int row = srow[r];
            ull key = 0ull;
#pragma unroll
            for (int c4 = 0; c4 < 4; c4++) {
                int code = tid + (c4 << 8);
                float d = g_ee[code] - 2.0f * acc[r][c4];   // shift-free
                float s = G[(size_t)row * KCODES + code] - d;
                key = max(key, packKey(s, code));
            }
#pragma unroll
            for (int off = 16; off; off >>= 1)
                key = max(key, __shfl_down_sync(0xFFFFFFFFu, key, off));
            if (lane == 0) rwarp[tid >> 5] = key;
            __syncthreads();
            if (tid == 0) {
                ull b2 = rwarp[0];
#pragma unroll
                for (int w = 1; w < 8; w++) b2 = max(b2, rwarp[w]);
                g_rowIdx[row] = 1023 - (int)(unsigned)(b2 & 0xFFFFFFFFull);
            }
            __syncthreads();
        }
    }
}

// ---------------- finish: one-hot scatter, quantized NCHW, histogram ----------
__global__ __launch_bounds__(256)
void finishKernel(const float* __restrict__ E, float* __restrict__ out) {
    __shared__ int   sIdx[32];
    __shared__ float sQ[32 * 257];

    const int n0  = blockIdx.x << 5;
    const int tid = threadIdx.x;

    if (tid < 32) {
        int idx = g_rowIdx[n0 + tid];
        sIdx[tid] = idx;
        out[ENC_OFF + (size_t)(n0 + tid) * KCODES + idx] = 1.0f;
        atomicAdd(&g_counts[idx], 1u);
    }
    __syncthreads();

    const int c = tid;
#pragma unroll 4
    for (int i = 0; i < 32; i++)
        sQ[i * 257 + c] = E[(size_t)sIdx[i] * CDIM + c];
    __syncthreads();

    const int b   = n0 >> 10;
    const int hw0 = n0 & 1023;
    float* qb = out + QUANT_OFF + (size_t)b * CDIM * HWDIM;
#pragma unroll 4
    for (int it = 0; it < 32; it++) {
        int f  = it * 256 + tid;
        int cc = f >> 5;
        int ii = f & 31;
        qb[(size_t)cc * HWDIM + hw0 + ii] = sQ[ii * 257 + cc];
    }
}

// ---------------- scalars ----------------
// loss = C*(kld + e_lat*stopgrad(kld/clip(e_lat,1e-8))); e_lat >> 1e-8 always,
// so ratio == 1 exactly and loss = 3*kld.
__global__ void lossKernel(float* __restrict__ out) {
    __shared__ float red[32];
    int t = threadIdx.x;
    float avg  = (float)g_counts[t] * (1.0f / 32768.0f);
    float term = avg * logf(avg + 1e-10f);
#pragma unroll
    for (int off = 16; off; off >>= 1) term += __shfl_down_sync(0xFFFFFFFFu, term, off);
    if ((t & 31) == 0) red[t >> 5] = term;
    __syncthreads();
    if (t < 32) {
        float v = red[t];
#pragma unroll
        for (int off = 16; off; off >>= 1) v += __shfl_down_sync(0xFFFFFFFFu, v, off);
        if (t == 0) {
            float kld = g_kldSum * (1.0f / 32768.0f);
            out[0]        = 3.0f * kld;
            out[PERP_OFF] = expf(-v);
        }
    }
}

// ---------------- launch ----------------
extern "C" void kernel_launch(void* const* d_in, const int* in_sizes, int n_in,
                              void* d_out, int out_size) {
    const float* inp = (const float*)d_in[0];
    const float* emb = (const float*)d_in[1];
    const float* gum = (const float*)d_in[2];
    float* out = (float*)d_out;
    float* enc = out + ENC_OFF;

    cudaFuncSetAttribute(gemmKernel, cudaFuncAttributeMaxDynamicSharedMemorySize, SMEM_DYN);

    prepE<<<256, 256>>>(emb);
    gemmKernel<<<dim3(KCODES / 128, N_ROWS / 64), 256, SMEM_DYN>>>(inp, gum, enc);
    argmaxKernel<<<N_ROWS / 8, 256>>>(inp, emb, gum);
    rescueKernel<<<512, 256>>>(inp, gum);
    finishKernel<<<N_ROWS / 32, 256>>>(emb, out);
    lossKernel<<<1, 1024>>>(out);
}